// round 6
// baseline (speedup 1.0000x reference)
#include <cuda_runtime.h>
#include <math.h>

// ---------------------------------------------------------------------------
// CapsuleModel2: out = sigmoid(mean_seg(caps[pidx]) @ W + b)
//
// Fast path (D=272, NC=19):
//   phase 1 proj: proj[R,20] = caps[R,272] @ W[272,19]   (f32x2, d-pair packed)
//   phase 2 pool: per-segment binary-search bounds + gather-sum of proj rows
// R5 -> R6: seg_bounds kernel removed from fast path (pool binary-searches),
//           proj inner loop repacked over d-pairs (no dup MOVs, 26 instr per
//           16 FMA2 vs 34), pool widened to 256 threads.
// ---------------------------------------------------------------------------

#define MAX_SEGS (1 << 17)
#define MAX_R    65536
__device__ int   g_seg_off[MAX_SEGS + 1];
__device__ float g_proj[(size_t)MAX_R * 20];

// ---------------------------------------------------------------- f32x2 utils
__device__ __forceinline__ void fma2(unsigned long long& d,
                                     unsigned long long a,
                                     unsigned long long b) {
    asm("fma.rn.f32x2 %0, %1, %2, %0;" : "+l"(d) : "l"(a), "l"(b));
}
__device__ __forceinline__ float2 unpack2(unsigned long long v) {
    unsigned int lo, hi;
    asm("mov.b64 {%0, %1}, %2;" : "=r"(lo), "=r"(hi) : "l"(v));
    return make_float2(__uint_as_float(lo), __uint_as_float(hi));
}

// ---------------------------------------------------------------- phase 1
// proj = caps @ W, D=272, NC=19(->20). TILE=64 rows, 160 thr = 32 row-slots
// x 5 class-groups (4 classes each). Thread: rows (rs, rs+32) x classes
// (4g..4g+3), accumulating f32x2 over (even-d, odd-d) pairs.
//   caps_s: float4 [64][69]  (odd stride -> conflict-free LDS.128)
//   Wt    : ull    [136][20] (Wt[d2][c] = (W[2d2][c], W[2d2+1][c]))
#define P1_BLOCK 160
#define P1_TILE  64
#define P1_SMEM  (P1_TILE * 69 * 16 + 136 * 20 * 8)

__global__ void __launch_bounds__(P1_BLOCK)
proj_kernel(const float4* __restrict__ caps4,   // [R][68]
            const float*  __restrict__ Wm,      // [272][19]
            int ntiles) {
    extern __shared__ float sm[];
    float4*             caps_s = (float4*)sm;                   // [64][69]
    unsigned long long* Wt     = (unsigned long long*)(sm + P1_TILE * 69 * 4);

    const int tid = threadIdx.x;

    // stage Wt once per CTA: pair (W[2d2][c], W[2d2+1][c]); c==19 -> 0
    {
        float* Wtf = (float*)Wt;
        for (int i = tid; i < 136 * 20; i += P1_BLOCK) {
            int d2 = i / 20, c = i % 20;
            float lo = (c < 19) ? Wm[(2 * d2) * 19 + c]     : 0.0f;
            float hi = (c < 19) ? Wm[(2 * d2 + 1) * 19 + c] : 0.0f;
            Wtf[2 * i]     = lo;
            Wtf[2 * i + 1] = hi;
        }
    }

    const int rs = tid & 31;          // row slot
    const int g  = tid >> 5;          // class group 0..4, classes 4g..4g+3

    for (int tile = blockIdx.x; tile < ntiles; tile += gridDim.x) {
        __syncthreads();              // previous compute done with caps_s
        const float4* src = caps4 + (size_t)tile * P1_TILE * 68;
        for (int i = tid; i < P1_TILE * 68; i += P1_BLOCK) {
            int r = i / 68, d4 = i % 68;
            caps_s[r * 69 + d4] = src[(size_t)r * 68 + d4];
        }
        __syncthreads();

        unsigned long long acc0[4] = {0ull, 0ull, 0ull, 0ull};  // row rs
        unsigned long long acc1[4] = {0ull, 0ull, 0ull, 0ull};  // row rs+32
        const float4* row0 = caps_s + rs * 69;
        const float4* row1 = caps_s + (rs + 32) * 69;

        #pragma unroll 4
        for (int d4 = 0; d4 < 68; ++d4) {
            // float4 = 2 d-pairs, reinterpret: .x = (v.x,v.y), .y = (v.z,v.w)
            ulonglong2 x0 = *reinterpret_cast<const ulonglong2*>(row0 + d4);
            ulonglong2 x1 = *reinterpret_cast<const ulonglong2*>(row1 + d4);
            const unsigned long long* w = Wt + d4 * 2 * 20 + 4 * g;
            #pragma unroll
            for (int c = 0; c < 4; ++c) {
                unsigned long long w0 = w[c];        // d2 = 2*d4
                unsigned long long w1 = w[20 + c];   // d2 = 2*d4+1
                fma2(acc0[c], x0.x, w0);
                fma2(acc1[c], x1.x, w0);
                fma2(acc0[c], x0.y, w1);
                fma2(acc1[c], x1.y, w1);
            }
        }

        const size_t r0 = ((size_t)tile * P1_TILE + rs) * 20 + 4 * g;
        const size_t r1 = r0 + 32 * 20;
        #pragma unroll
        for (int c = 0; c < 4; ++c) {
            float2 f0 = unpack2(acc0[c]);
            float2 f1 = unpack2(acc1[c]);
            g_proj[r0 + c] = f0.x + f0.y;
            g_proj[r1 + c] = f1.x + f1.y;
        }
    }
}

// ---------------------------------------------------------------- phase 2
// One CTA (256 thr) per segment; bounds via binary search on sorted segid.
// 32 groups x 8 lanes; 5 active lanes read the point's 5 float4 (80B row).
__global__ void __launch_bounds__(256)
pool_kernel(const int* __restrict__ pidx,
            const int* __restrict__ segid,
            const float* __restrict__ bias,
            float* __restrict__ out,
            int P) {
    const int seg = blockIdx.x;
    const int tid = threadIdx.x;

    __shared__ int sb[2];
    if (tid < 2) {
        int target = seg + tid;
        int lo = 0, hi = P;
        while (lo < hi) {
            int mid = (lo + hi) >> 1;
            if (segid[mid] < target) lo = mid + 1; else hi = mid;
        }
        sb[tid] = lo;
    }
    __syncthreads();
    const int start = sb[0];
    const int end   = sb[1];

    const int grp = tid >> 3;         // 0..31
    const int sub = tid & 7;          // f4 slot if < 5

    const float4* proj4 = (const float4*)g_proj;
    float4 acc = make_float4(0.f, 0.f, 0.f, 0.f);

    for (int p = start + grp; p < end; p += 32) {
        int row = __ldg(&pidx[p]);
        if (sub < 5) {
            float4 v = proj4[(size_t)row * 5 + sub];
            acc.x += v.x; acc.y += v.y; acc.z += v.z; acc.w += v.w;
        }
    }

    // combine the 4 groups within each warp (lanes l, l+8, l+16, l+24)
    #pragma unroll
    for (int off = 16; off >= 8; off >>= 1) {
        acc.x += __shfl_down_sync(0xFFFFFFFFu, acc.x, off);
        acc.y += __shfl_down_sync(0xFFFFFFFFu, acc.y, off);
        acc.z += __shfl_down_sync(0xFFFFFFFFu, acc.z, off);
        acc.w += __shfl_down_sync(0xFFFFFFFFu, acc.w, off);
    }

    __shared__ float wt[8][32];       // 8 warps x (8 slots x 4 comps)
    const int lane = tid & 31, w = tid >> 5;
    if (lane < 8) {
        wt[w][lane * 4 + 0] = acc.x;
        wt[w][lane * 4 + 1] = acc.y;
        wt[w][lane * 4 + 2] = acc.z;
        wt[w][lane * 4 + 3] = acc.w;
    }
    __syncthreads();

    if (tid < 19) {
        const float inv = 1.0f / fmaxf((float)(end - start), 1.0f);
        float s = 0.f;
        #pragma unroll
        for (int k = 0; k < 8; ++k) s += wt[k][tid];
        float logit = s * inv + bias[tid];
        out[(size_t)seg * 19 + tid] = 1.0f / (1.0f + __expf(-logit));
    }
}

// ================================================================ fallback
__global__ void seg_bounds_kernel(const int* __restrict__ seg, int P, int NI) {
    int p = blockIdx.x * blockDim.x + threadIdx.x;
    if (p >= P) return;
    int s = seg[p];
    if (p == 0) {
        for (int k = 0; k <= s; ++k) g_seg_off[k] = 0;
    } else {
        int prev = seg[p - 1];
        for (int k = prev + 1; k <= s; ++k) g_seg_off[k] = p;
    }
    if (p == P - 1) {
        for (int k = s + 1; k <= NI; ++k) g_seg_off[k] = P;
    }
}

template <int D4>
__global__ void __launch_bounds__(256)
capsule_vec_kernel(const float4* __restrict__ caps4,
                   const float* __restrict__ Wm,
                   const float* __restrict__ bias,
                   const int* __restrict__ pidx,
                   float* __restrict__ out,
                   int NC) {
    const int seg    = blockIdx.x;
    const int tid    = threadIdx.x;
    const int team   = tid >> 6;
    const int lane64 = tid & 63;
    const int start  = g_seg_off[seg];
    const int end    = g_seg_off[seg + 1];

    const int col0 = lane64;
    const int col1 = 64 + lane64;
    const bool has1 = col1 < D4;

    __shared__ int sidx[256];
    __shared__ float4 sred[D4 * 4];
    float* pooled = (float*)sred;

    float4 acc0 = make_float4(0.f, 0.f, 0.f, 0.f);
    float4 acc1 = make_float4(0.f, 0.f, 0.f, 0.f);

    for (int base = start; base < end; base += 256) {
        const int n = min(256, end - base);
        if (tid < n) sidx[tid] = pidx[base + tid];
        __syncthreads();
        int i = team;
        for (; i + 12 < n; i += 16) {
            const float4* r0 = caps4 + (size_t)sidx[i +  0] * D4;
            const float4* r1 = caps4 + (size_t)sidx[i +  4] * D4;
            const float4* r2 = caps4 + (size_t)sidx[i +  8] * D4;
            const float4* r3 = caps4 + (size_t)sidx[i + 12] * D4;
            float4 a0 = r0[col0], a1 = r1[col0], a2 = r2[col0], a3 = r3[col0];
            acc0.x += (a0.x + a1.x) + (a2.x + a3.x);
            acc0.y += (a0.y + a1.y) + (a2.y + a3.y);
            acc0.z += (a0.z + a1.z) + (a2.z + a3.z);
            acc0.w += (a0.w + a1.w) + (a2.w + a3.w);
            if (has1) {
                float4 b0 = r0[col1], b1 = r1[col1], b2 = r2[col1], b3 = r3[col1];
                acc1.x += (b0.x + b1.x) + (b2.x + b3.x);
                acc1.y += (b0.y + b1.y) + (b2.y + b3.y);
                acc1.z += (b0.z + b1.z) + (b2.z + b3.z);
                acc1.w += (b0.w + b1.w) + (b2.w + b3.w);
            }
        }
        for (; i < n; i += 4) {
            const float4* r = caps4 + (size_t)sidx[i] * D4;
            float4 v = r[col0];
            acc0.x += v.x; acc0.y += v.y; acc0.z += v.z; acc0.w += v.w;
            if (has1) {
                float4 w = r[col1];
                acc1.x += w.x; acc1.y += w.y; acc1.z += w.z; acc1.w += w.w;
            }
        }
        __syncthreads();
    }

    sred[col0 * 4 + team] = acc0;
    if (has1) sred[col1 * 4 + team] = acc1;
    __syncthreads();

    const float inv = 1.0f / fmaxf((float)(end - start), 1.0f);
    float4 p4;
    if (tid < D4) {
        float4 s0 = sred[tid * 4 + 0];
        float4 s1 = sred[tid * 4 + 1];
        float4 s2 = sred[tid * 4 + 2];
        float4 s3 = sred[tid * 4 + 3];
        p4.x = ((s0.x + s1.x) + (s2.x + s3.x)) * inv;
        p4.y = ((s0.y + s1.y) + (s2.y + s3.y)) * inv;
        p4.z = ((s0.z + s1.z) + (s2.z + s3.z)) * inv;
        p4.w = ((s0.w + s1.w) + (s2.w + s3.w)) * inv;
    }
    __syncthreads();
    if (tid < D4) {
        pooled[4 * tid + 0] = p4.x;
        pooled[4 * tid + 1] = p4.y;
        pooled[4 * tid + 2] = p4.z;
        pooled[4 * tid + 3] = p4.w;
    }
    __syncthreads();

    const int c = tid >> 3;
    const int j = tid & 7;
    if (c < NC) {
        const int D = D4 * 4;
        float s = (j == 0) ? bias[c] : 0.0f;
        for (int d = j; d < D; d += 8)
            s = fmaf(pooled[d], Wm[d * NC + c], s);
        s += __shfl_down_sync(0xFFFFFFFFu, s, 4);
        s += __shfl_down_sync(0xFFFFFFFFu, s, 2);
        s += __shfl_down_sync(0xFFFFFFFFu, s, 1);
        if (j == 0)
            out[(size_t)seg * NC + c] = 1.0f / (1.0f + __expf(-s));
    }
}

__global__ void __launch_bounds__(256)
capsule_scalar_kernel(const float* __restrict__ caps,
                      const float* __restrict__ Wm,
                      const float* __restrict__ bias,
                      const int* __restrict__ pidx,
                      float* __restrict__ out,
                      int D, int NC) {
    const int BLOCK = 256;
    const int seg = blockIdx.x;
    const int tid = threadIdx.x;
    const int start = g_seg_off[seg];
    const int end   = g_seg_off[seg + 1];

    __shared__ int sidx[256];
    extern __shared__ float pooled[];

    float acc[8];
    #pragma unroll
    for (int k = 0; k < 8; ++k) acc[k] = 0.f;

    for (int base = start; base < end; base += BLOCK) {
        int n = min(BLOCK, end - base);
        if (tid < n) sidx[tid] = pidx[base + tid];
        __syncthreads();
        for (int i = 0; i < n; ++i) {
            const float* row = caps + (size_t)sidx[i] * D;
            #pragma unroll
            for (int k = 0; k < 8; ++k) {
                int d = tid + k * BLOCK;
                if (d < D) acc[k] += row[d];
            }
        }
        __syncthreads();
    }

    const float inv = 1.0f / fmaxf((float)(end - start), 1.0f);
    #pragma unroll
    for (int k = 0; k < 8; ++k) {
        int d = tid + k * 256;
        if (d < D) pooled[d] = acc[k] * inv;
    }
    __syncthreads();

    if (tid < NC) {
        float s = bias[tid];
        for (int d = 0; d < D; ++d)
            s = fmaf(pooled[d], Wm[d * NC + tid], s);
        out[(size_t)seg * NC + tid] = 1.0f / (1.0f + __expf(-s));
    }
}

// ================================================================ launch
extern "C" void kernel_launch(void* const* d_in, const int* in_sizes, int n_in,
                              void* d_out, int out_size) {
    const float* caps  = (const float*)d_in[0];
    const float* Wm    = (const float*)d_in[1];
    const float* bias  = (const float*)d_in[2];
    const int*   pidx  = (const int*)d_in[3];
    const int*   segid = (const int*)d_in[4];
    float* out = (float*)d_out;

    const int NC = in_sizes[2];
    const int D  = in_sizes[1] / NC;
    const int P  = in_sizes[3];
    const int NI = out_size / NC;
    const int R  = in_sizes[0] / D;

    if (D == 272 && NC == 19 && R <= MAX_R && (R % P1_TILE) == 0) {
        cudaFuncSetAttribute(proj_kernel,
                             cudaFuncAttributeMaxDynamicSharedMemorySize,
                             P1_SMEM);
        proj_kernel<<<296, P1_BLOCK, P1_SMEM>>>(
            (const float4*)caps, Wm, R / P1_TILE);
        pool_kernel<<<NI, 256>>>(pidx, segid, bias, out, P);
    } else if (D == 272) {
        seg_bounds_kernel<<<(P + 255) / 256, 256>>>(segid, P, NI);
        capsule_vec_kernel<68><<<NI, 256>>>(
            (const float4*)caps, Wm, bias, pidx, out, NC);
    } else if (D == 256) {
        seg_bounds_kernel<<<(P + 255) / 256, 256>>>(segid, P, NI);
        capsule_vec_kernel<64><<<NI, 256>>>(
            (const float4*)caps, Wm, bias, pidx, out, NC);
    } else {
        seg_bounds_kernel<<<(P + 255) / 256, 256>>>(segid, P, NI);
        capsule_scalar_kernel<<<NI, 256, D * sizeof(float)>>>(
            caps, Wm, bias, pidx, out, D, NC);
    }
}

// round 12
// speedup vs baseline: 1.2025x; 1.2025x over previous
#include <cuda_runtime.h>
#include <math.h>

// ---------------------------------------------------------------------------
// CapsuleModel2: out = sigmoid(mean_seg(caps[pidx]) @ W + b)
//
// Fast path (D=272, NC=19):
//   proj: g_seg_off bounds prologue (grid-stride) + proj[R,20] = caps @ W
//         (f32x2 d-pair FMA2, 320 thr = 64 rows x 5 class-groups, 5 w/SMSP)
//   pool: per-segment CTA, prefetched independent gathers (no serial chains)
// R6 -> R12 (R7-R11 never ran: broker timeouts):
//           binary search removed (bounds fused into proj prologue),
//           pool prefetch (2 serial RTs instead of ~25), proj occupancy 2x.
// ---------------------------------------------------------------------------

#define MAX_SEGS (1 << 17)
#define MAX_R    65536
__device__ int   g_seg_off[MAX_SEGS + 1];
__device__ float g_proj[(size_t)MAX_R * 20];

// ---------------------------------------------------------------- f32x2 utils
__device__ __forceinline__ void fma2(unsigned long long& d,
                                     unsigned long long a,
                                     unsigned long long b) {
    asm("fma.rn.f32x2 %0, %1, %2, %0;" : "+l"(d) : "l"(a), "l"(b));
}
__device__ __forceinline__ float hadd2(unsigned long long v) {
    unsigned int lo, hi;
    asm("mov.b64 {%0, %1}, %2;" : "=r"(lo), "=r"(hi) : "l"(v));
    return __uint_as_float(lo) + __uint_as_float(hi);
}

// ---------------------------------------------------------------- phase 1
// 320 threads: rs = tid%64 (row slot), g = tid/64 (classes 4g..4g+3).
//   caps_s: float4 [64][69]   (odd stride -> conflict-free LDS.128)
//   Wt:     ull    [136][20]  (Wt[d2][c] = (W[2d2][c], W[2d2+1][c]))
#define P1_BLOCK 320
#define P1_TILE  64
#define P1_GRID  296
#define P1_SMEM  (P1_TILE * 69 * 16 + 136 * 20 * 8)

__global__ void __launch_bounds__(P1_BLOCK)
proj_kernel(const float4* __restrict__ caps4,   // [R][68]
            const float*  __restrict__ Wm,      // [272][19]
            const int*    __restrict__ segid,   // [P] sorted
            int ntiles, int P, int NI) {
    extern __shared__ float sm[];
    float4*             caps_s = (float4*)sm;                   // [64][69]
    unsigned long long* Wt     = (unsigned long long*)(sm + P1_TILE * 69 * 4);

    const int tid = threadIdx.x;

    // ---- prologue: segment bounds (grid-stride boundary detect) ----
    for (int p = blockIdx.x * P1_BLOCK + tid; p < P;
         p += gridDim.x * P1_BLOCK) {
        int s = segid[p];
        if (p == 0) {
            for (int k = 0; k <= s; ++k) g_seg_off[k] = 0;
        } else {
            int prev = segid[p - 1];
            for (int k = prev + 1; k <= s; ++k) g_seg_off[k] = p;
        }
        if (p == P - 1) {
            for (int k = s + 1; k <= NI; ++k) g_seg_off[k] = P;
        }
    }

    // ---- stage Wt once per CTA: (W[2d2][c], W[2d2+1][c]); c==19 -> 0 ----
    {
        float* Wtf = (float*)Wt;
        for (int i = tid; i < 136 * 20; i += P1_BLOCK) {
            int d2 = i / 20, c = i % 20;
            Wtf[2 * i]     = (c < 19) ? Wm[(2 * d2) * 19 + c]     : 0.0f;
            Wtf[2 * i + 1] = (c < 19) ? Wm[(2 * d2 + 1) * 19 + c] : 0.0f;
        }
    }

    const int rs = tid % 64;
    const int g  = tid / 64;          // 0..4

    for (int tile = blockIdx.x; tile < ntiles; tile += gridDim.x) {
        __syncthreads();              // caps_s free (also covers Wt on iter 0)
        const float4* src = caps4 + (size_t)tile * P1_TILE * 68;
        for (int i = tid; i < P1_TILE * 68; i += P1_BLOCK) {
            int r = i / 68, d4 = i % 68;
            caps_s[r * 69 + d4] = src[(size_t)r * 68 + d4];
        }
        __syncthreads();

        unsigned long long acc[4] = {0ull, 0ull, 0ull, 0ull};
        const ulonglong2* row = (const ulonglong2*)(caps_s + rs * 69);

        #pragma unroll 4
        for (int d4 = 0; d4 < 68; ++d4) {
            ulonglong2 x = row[d4];   // (d-pair 2d4, d-pair 2d4+1)
            const ulonglong2* wA =
                (const ulonglong2*)(Wt + (2 * d4) * 20 + 4 * g);
            const ulonglong2* wB =
                (const ulonglong2*)(Wt + (2 * d4 + 1) * 20 + 4 * g);
            ulonglong2 wa0 = wA[0], wa1 = wA[1];
            ulonglong2 wb0 = wB[0], wb1 = wB[1];
            fma2(acc[0], x.x, wa0.x);
            fma2(acc[1], x.x, wa0.y);
            fma2(acc[2], x.x, wa1.x);
            fma2(acc[3], x.x, wa1.y);
            fma2(acc[0], x.y, wb0.x);
            fma2(acc[1], x.y, wb0.y);
            fma2(acc[2], x.y, wb1.x);
            fma2(acc[3], x.y, wb1.y);
        }

        float4 o;
        o.x = hadd2(acc[0]);
        o.y = hadd2(acc[1]);
        o.z = hadd2(acc[2]);
        o.w = hadd2(acc[3]);
        *(float4*)(&g_proj[((size_t)tile * P1_TILE + rs) * 20 + 4 * g]) = o;
    }
}

// ---------------------------------------------------------------- phase 2
// One CTA (256 thr) per segment. 32 groups x 8 lanes; 5 active lanes read
// the point's 5 float4. All index loads prefetched (independent), then all
// gathers issued (independent) -> 2 serial round trips total.
__global__ void __launch_bounds__(256)
pool_kernel(const int* __restrict__ pidx,
            const float* __restrict__ bias,
            float* __restrict__ out) {
    const int seg   = blockIdx.x;
    const int tid   = threadIdx.x;
    const int grp   = tid >> 3;       // 0..31
    const int sub   = tid & 7;        // f4 slot if < 5
    const int start = g_seg_off[seg];
    const int end   = g_seg_off[seg + 1];

    const float4* proj4 = (const float4*)g_proj;
    float4 acc = make_float4(0.f, 0.f, 0.f, 0.f);

    // prefetch up to 6 strided indices (covers segments up to 192 points)
    int rows[6];
    #pragma unroll
    for (int k = 0; k < 6; ++k) {
        int p = start + grp + k * 32;
        rows[k] = (p < end) ? __ldg(&pidx[p]) : -1;
    }
    #pragma unroll
    for (int k = 0; k < 6; ++k) {
        if (rows[k] >= 0 && sub < 5) {
            float4 v = proj4[(size_t)rows[k] * 5 + sub];
            acc.x += v.x; acc.y += v.y; acc.z += v.z; acc.w += v.w;
        }
    }
    // rare tail for very large segments
    for (int p = start + grp + 192; p < end; p += 32) {
        int row = __ldg(&pidx[p]);
        if (sub < 5) {
            float4 v = proj4[(size_t)row * 5 + sub];
            acc.x += v.x; acc.y += v.y; acc.z += v.z; acc.w += v.w;
        }
    }

    // combine the 4 groups within each warp (lanes l, l+8, l+16, l+24)
    #pragma unroll
    for (int off = 16; off >= 8; off >>= 1) {
        acc.x += __shfl_down_sync(0xFFFFFFFFu, acc.x, off);
        acc.y += __shfl_down_sync(0xFFFFFFFFu, acc.y, off);
        acc.z += __shfl_down_sync(0xFFFFFFFFu, acc.z, off);
        acc.w += __shfl_down_sync(0xFFFFFFFFu, acc.w, off);
    }

    __shared__ float wt[8][32];       // 8 warps x (8 slots x 4 comps)
    const int lane = tid & 31, w = tid >> 5;
    if (lane < 8) {
        wt[w][lane * 4 + 0] = acc.x;
        wt[w][lane * 4 + 1] = acc.y;
        wt[w][lane * 4 + 2] = acc.z;
        wt[w][lane * 4 + 3] = acc.w;
    }
    __syncthreads();

    if (tid < 19) {
        const float inv = 1.0f / fmaxf((float)(end - start), 1.0f);
        float s = 0.f;
        #pragma unroll
        for (int k = 0; k < 8; ++k) s += wt[k][tid];
        float logit = s * inv + bias[tid];
        out[(size_t)seg * 19 + tid] = 1.0f / (1.0f + __expf(-logit));
    }
}

// ================================================================ fallback
__global__ void seg_bounds_kernel(const int* __restrict__ seg, int P, int NI) {
    int p = blockIdx.x * blockDim.x + threadIdx.x;
    if (p >= P) return;
    int s = seg[p];
    if (p == 0) {
        for (int k = 0; k <= s; ++k) g_seg_off[k] = 0;
    } else {
        int prev = seg[p - 1];
        for (int k = prev + 1; k <= s; ++k) g_seg_off[k] = p;
    }
    if (p == P - 1) {
        for (int k = s + 1; k <= NI; ++k) g_seg_off[k] = P;
    }
}

template <int D4>
__global__ void __launch_bounds__(256)
capsule_vec_kernel(const float4* __restrict__ caps4,
                   const float* __restrict__ Wm,
                   const float* __restrict__ bias,
                   const int* __restrict__ pidx,
                   float* __restrict__ out,
                   int NC) {
    const int seg    = blockIdx.x;
    const int tid    = threadIdx.x;
    const int team   = tid >> 6;
    const int lane64 = tid & 63;
    const int start  = g_seg_off[seg];
    const int end    = g_seg_off[seg + 1];

    const int col0 = lane64;
    const int col1 = 64 + lane64;
    const bool has1 = col1 < D4;

    __shared__ int sidx[256];
    __shared__ float4 sred[D4 * 4];
    float* pooled = (float*)sred;

    float4 acc0 = make_float4(0.f, 0.f, 0.f, 0.f);
    float4 acc1 = make_float4(0.f, 0.f, 0.f, 0.f);

    for (int base = start; base < end; base += 256) {
        const int n = min(256, end - base);
        if (tid < n) sidx[tid] = pidx[base + tid];
        __syncthreads();
        int i = team;
        for (; i + 12 < n; i += 16) {
            const float4* r0 = caps4 + (size_t)sidx[i +  0] * D4;
            const float4* r1 = caps4 + (size_t)sidx[i +  4] * D4;
            const float4* r2 = caps4 + (size_t)sidx[i +  8] * D4;
            const float4* r3 = caps4 + (size_t)sidx[i + 12] * D4;
            float4 a0 = r0[col0], a1 = r1[col0], a2 = r2[col0], a3 = r3[col0];
            acc0.x += (a0.x + a1.x) + (a2.x + a3.x);
            acc0.y += (a0.y + a1.y) + (a2.y + a3.y);
            acc0.z += (a0.z + a1.z) + (a2.z + a3.z);
            acc0.w += (a0.w + a1.w) + (a2.w + a3.w);
            if (has1) {
                float4 b0 = r0[col1], b1 = r1[col1], b2 = r2[col1], b3 = r3[col1];
                acc1.x += (b0.x + b1.x) + (b2.x + b3.x);
                acc1.y += (b0.y + b1.y) + (b2.y + b3.y);
                acc1.z += (b0.z + b1.z) + (b2.z + b3.z);
                acc1.w += (b0.w + b1.w) + (b2.w + b3.w);
            }
        }
        for (; i < n; i += 4) {
            const float4* r = caps4 + (size_t)sidx[i] * D4;
            float4 v = r[col0];
            acc0.x += v.x; acc0.y += v.y; acc0.z += v.z; acc0.w += v.w;
            if (has1) {
                float4 w = r[col1];
                acc1.x += w.x; acc1.y += w.y; acc1.z += w.z; acc1.w += w.w;
            }
        }
        __syncthreads();
    }

    sred[col0 * 4 + team] = acc0;
    if (has1) sred[col1 * 4 + team] = acc1;
    __syncthreads();

    const float inv = 1.0f / fmaxf((float)(end - start), 1.0f);
    float4 p4;
    if (tid < D4) {
        float4 s0 = sred[tid * 4 + 0];
        float4 s1 = sred[tid * 4 + 1];
        float4 s2 = sred[tid * 4 + 2];
        float4 s3 = sred[tid * 4 + 3];
        p4.x = ((s0.x + s1.x) + (s2.x + s3.x)) * inv;
        p4.y = ((s0.y + s1.y) + (s2.y + s3.y)) * inv;
        p4.z = ((s0.z + s1.z) + (s2.z + s3.z)) * inv;
        p4.w = ((s0.w + s1.w) + (s2.w + s3.w)) * inv;
    }
    __syncthreads();
    if (tid < D4) {
        pooled[4 * tid + 0] = p4.x;
        pooled[4 * tid + 1] = p4.y;
        pooled[4 * tid + 2] = p4.z;
        pooled[4 * tid + 3] = p4.w;
    }
    __syncthreads();

    const int c = tid >> 3;
    const int j = tid & 7;
    if (c < NC) {
        const int D = D4 * 4;
        float s = (j == 0) ? bias[c] : 0.0f;
        for (int d = j; d < D; d += 8)
            s = fmaf(pooled[d], Wm[d * NC + c], s);
        s += __shfl_down_sync(0xFFFFFFFFu, s, 4);
        s += __shfl_down_sync(0xFFFFFFFFu, s, 2);
        s += __shfl_down_sync(0xFFFFFFFFu, s, 1);
        if (j == 0)
            out[(size_t)seg * NC + c] = 1.0f / (1.0f + __expf(-s));
    }
}

__global__ void __launch_bounds__(256)
capsule_scalar_kernel(const float* __restrict__ caps,
                      const float* __restrict__ Wm,
                      const float* __restrict__ bias,
                      const int* __restrict__ pidx,
                      float* __restrict__ out,
                      int D, int NC) {
    const int BLOCK = 256;
    const int seg = blockIdx.x;
    const int tid = threadIdx.x;
    const int start = g_seg_off[seg];
    const int end   = g_seg_off[seg + 1];

    __shared__ int sidx[256];
    extern __shared__ float pooled[];

    float acc[8];
    #pragma unroll
    for (int k = 0; k < 8; ++k) acc[k] = 0.f;

    for (int base = start; base < end; base += BLOCK) {
        int n = min(BLOCK, end - base);
        if (tid < n) sidx[tid] = pidx[base + tid];
        __syncthreads();
        for (int i = 0; i < n; ++i) {
            const float* row = caps + (size_t)sidx[i] * D;
            #pragma unroll
            for (int k = 0; k < 8; ++k) {
                int d = tid + k * BLOCK;
                if (d < D) acc[k] += row[d];
            }
        }
        __syncthreads();
    }

    const float inv = 1.0f / fmaxf((float)(end - start), 1.0f);
    #pragma unroll
    for (int k = 0; k < 8; ++k) {
        int d = tid + k * 256;
        if (d < D) pooled[d] = acc[k] * inv;
    }
    __syncthreads();

    if (tid < NC) {
        float s = bias[tid];
        for (int d = 0; d < D; ++d)
            s = fmaf(pooled[d], Wm[d * NC + tid], s);
        out[(size_t)seg * NC + tid] = 1.0f / (1.0f + __expf(-s));
    }
}

// ================================================================ launch
extern "C" void kernel_launch(void* const* d_in, const int* in_sizes, int n_in,
                              void* d_out, int out_size) {
    const float* caps  = (const float*)d_in[0];
    const float* Wm    = (const float*)d_in[1];
    const float* bias  = (const float*)d_in[2];
    const int*   pidx  = (const int*)d_in[3];
    const int*   segid = (const int*)d_in[4];
    float* out = (float*)d_out;

    const int NC = in_sizes[2];
    const int D  = in_sizes[1] / NC;
    const int P  = in_sizes[3];
    const int NI = out_size / NC;
    const int R  = in_sizes[0] / D;

    if (D == 272 && NC == 19 && R <= MAX_R && (R % P1_TILE) == 0 &&
        NI < MAX_SEGS) {
        cudaFuncSetAttribute(proj_kernel,
                             cudaFuncAttributeMaxDynamicSharedMemorySize,
                             P1_SMEM);
        proj_kernel<<<P1_GRID, P1_BLOCK, P1_SMEM>>>(
            (const float4*)caps, Wm, segid, R / P1_TILE, P, NI);
        pool_kernel<<<NI, 256>>>(pidx, bias, out);
    } else if (D == 272) {
        seg_bounds_kernel<<<(P + 255) / 256, 256>>>(segid, P, NI);
        capsule_vec_kernel<68><<<NI, 256>>>(
            (const float4*)caps, Wm, bias, pidx, out, NC);
    } else if (D == 256) {
        seg_bounds_kernel<<<(P + 255) / 256, 256>>>(segid, P, NI);
        capsule_vec_kernel<64><<<NI, 256>>>(
            (const float4*)caps, Wm, bias, pidx, out, NC);
    } else {
        seg_bounds_kernel<<<(P + 255) / 256, 256>>>(segid, P, NI);
        capsule_scalar_kernel<<<NI, 256, D * sizeof(float)>>>(
            caps, Wm, bias, pidx, out, D, NC);
    }
}